// round 12
// baseline (speedup 1.0000x reference)
#include <cuda_runtime.h>
#include <cuda_fp16.h>
#include <cstdint>
#include <math.h>

#define B_   256
#define T_   512
#define D_   128
#define H_   1024
#define G_   3072
#define O_   128
#define DIN  257
#define KIN  320

// ---- gi GEMM tiling ----
#define BKS     64
#define SPH     72
#define A_HL    (64 * SPH)
#define B_HL    (96 * SPH)
#define STG_HL  (A_HL + B_HL)
#define GI_SMEM (4 * STG_HL * 2)

// ---- persistent kernel smem ----
#define WCH     12288
#define W_SM    (16 * WCH)
#define AST     8192
#define P_SMEM  (W_SM + 4 * AST)

// ---------------- scratch ----------------
__device__ float  g_gi[(size_t)T_ * B_ * G_];
__device__ __half g_xh[(size_t)(T_ * B_) * KIN];
__device__ __half g_wih[(size_t)G_ * KIN];
__device__ __half g_w3[(size_t)G_ * H_];
__device__ float  g_hf[2][B_ * H_];
__device__ __half g_hh[2][B_ * H_];
__device__ unsigned g_bars[64];

// ---------------- helpers ----------------
__device__ __forceinline__ float fsig(float x) {
    float e; asm("ex2.approx.f32 %0, %1;" : "=f"(e) : "f"(-1.4426950408889634f * x));
    float r; asm("rcp.approx.f32 %0, %1;" : "=f"(r) : "f"(1.0f + e));
    return r;
}
__device__ __forceinline__ float ftanh_(float x) {
    float e; asm("ex2.approx.f32 %0, %1;" : "=f"(e) : "f"(-2.8853900817779268f * x));
    float r; asm("rcp.approx.f32 %0, %1;" : "=f"(r) : "f"(1.0f + e));
    return 2.0f * r - 1.0f;
}
__device__ __forceinline__ uint32_t smem_u32(const void* p) {
    uint32_t a; asm("{ .reg .u64 t; cvta.to.shared.u64 t, %1; cvt.u32.u64 %0, t; }" : "=r"(a) : "l"(p)); return a;
}
__device__ __forceinline__ void cpa16(uint32_t d, const void* s) {
    asm volatile("cp.async.cg.shared.global [%0], [%1], 16;" :: "r"(d), "l"(s));
}
__device__ __forceinline__ void cpcommit() { asm volatile("cp.async.commit_group;"); }
__device__ __forceinline__ void cpwait2()  { asm volatile("cp.async.wait_group 2;" ::: "memory"); }
__device__ __forceinline__ void cpwait0()  { asm volatile("cp.async.wait_group 0;" ::: "memory"); }

#define LDSM4(r0, r1, r2, r3, addr) \
    asm volatile("ldmatrix.sync.aligned.m8n8.x4.shared.b16 {%0,%1,%2,%3}, [%4];" \
        : "=r"(r0), "=r"(r1), "=r"(r2), "=r"(r3) : "r"(addr))
#define LDSM2(r0, r1, addr) \
    asm volatile("ldmatrix.sync.aligned.m8n8.x2.shared.b16 {%0,%1}, [%2];" \
        : "=r"(r0), "=r"(r1) : "r"(addr))

__device__ __forceinline__ void mma_f16(float* d, uint32_t a0, uint32_t a1, uint32_t a2, uint32_t a3,
                                        uint32_t b0, uint32_t b1) {
    asm volatile("mma.sync.aligned.m16n8k16.row.col.f32.f16.f16.f32 "
        "{%0,%1,%2,%3},{%4,%5,%6,%7},{%8,%9},{%0,%1,%2,%3};\n"
        : "+f"(d[0]), "+f"(d[1]), "+f"(d[2]), "+f"(d[3])
        : "r"(a0), "r"(a1), "r"(a2), "r"(a3), "r"(b0), "r"(b1));
}

// ---------------- gi GEMM mainloop (proven, unchanged) ----------------
template<int NSTG>
__device__ __forceinline__ void mainloop16(
    uint32_t sbase,
    const __half* __restrict__ Ag, int lda,
    const __half* __restrict__ B0, const __half* __restrict__ B1,
    const __half* __restrict__ B2, int ldb,
    int tid, int wm, int wn, float acc[2][3][4])
{
    const int lane = tid & 31;
    const int lrow = lane & 15, lcol = (lane >> 4) << 3;
    const uint32_t aoff = (uint32_t)(((wm + lrow) * SPH + lcol) * 2);
    const int b4row = wn + ((lane >> 4) << 3) + (lane & 7);
    const int bcol = ((lane >> 3) & 1) << 3;
    const uint32_t b4off = (uint32_t)((b4row * SPH + bcol) * 2);
    const int b2row = wn + 16 + (lane & 7);
    const uint32_t b2off = (uint32_t)((b2row * SPH + bcol) * 2);

    auto issue = [&](int s) {
        int buf = s & 3;
        uint32_t ab = sbase + (uint32_t)(buf * STG_HL) * 2u;
        uint32_t bb = ab + A_HL * 2u;
        int kc = s * BKS;
#pragma unroll
        for (int i = 0; i < 2; i++) {
            int f = tid + 256 * i, r = f >> 3, c4 = f & 7;
            cpa16(ab + (uint32_t)(r * SPH + c4 * 8) * 2u, Ag + (size_t)r * lda + kc + c4 * 8);
        }
#pragma unroll
        for (int i = 0; i < 3; i++) {
            int f = tid + 256 * i, r = f >> 3, c4 = f & 7;
            const __half* base = (r < 32) ? B0 : ((r < 64) ? B1 : B2);
            cpa16(bb + (uint32_t)(r * SPH + c4 * 8) * 2u, base + (size_t)(r & 31) * ldb + kc + c4 * 8);
        }
        cpcommit();
    };

    issue(0); issue(1); issue(2);
#pragma unroll 1
    for (int s = 0; s < NSTG; s++) {
        cpwait2();
        __syncthreads();
        uint32_t ab = sbase + (uint32_t)((s & 3) * STG_HL) * 2u;
        uint32_t bb = ab + A_HL * 2u;
#pragma unroll
        for (int g = 0; g < 4; g++) {
            const uint32_t gof = (uint32_t)(g * 16 * 2);
            uint32_t A0[4], A1[4], Bb[6];
            LDSM4(A0[0], A0[1], A0[2], A0[3], ab + aoff + gof);
            LDSM4(A1[0], A1[1], A1[2], A1[3], ab + aoff + (uint32_t)(16 * SPH * 2) + gof);
            LDSM4(Bb[0], Bb[1], Bb[2], Bb[3], bb + b4off + gof);
            LDSM2(Bb[4], Bb[5], bb + b2off + gof);
#pragma unroll
            for (int nf = 0; nf < 3; nf++) {
                mma_f16(acc[0][nf], A0[0], A0[1], A0[2], A0[3], Bb[2 * nf], Bb[2 * nf + 1]);
                mma_f16(acc[1][nf], A1[0], A1[1], A1[2], A1[3], Bb[2 * nf], Bb[2 * nf + 1]);
            }
        }
        if (s + 3 < NSTG) issue(s + 3); else cpcommit();
    }
    cpwait0();
    __syncthreads();
}

// ---------------- fused pack kernel ----------------
#define NBX  163840
#define NBW3 12288
#define NBW  3840
#define NBZ  1024
__global__ void pack_fused(const float* __restrict__ x, const float* __restrict__ mask,
                           const float* __restrict__ ti, const float* __restrict__ W_ih,
                           const float* __restrict__ W_hh) {
    long long bid = blockIdx.x;
    int tidl = threadIdx.x;
    if (bid < NBX) {
        size_t idx = (size_t)bid * 256 + tidl;
        int k = (int)(idx % KIN);
        size_t row = idx / KIN;
        int t = (int)(row >> 8), b = (int)(row & 255);
        float v = 0.f;
        if (k < 128) v = x[((size_t)b * T_ + t) * D_ + k];
        else if (k < 256) v = mask[((size_t)b * T_ + t) * D_ + (k - 128)];
        else if (k == 256) v = ti[(size_t)b * T_ + t];
        g_xh[idx] = __float2half_rn(v);
    } else if (bid < NBX + NBW3) {
        size_t idx = (size_t)(bid - NBX) * 256 + tidl;
        g_w3[idx] = __float2half_rn(W_hh[idx]);
    } else if (bid < NBX + NBW3 + NBW) {
        size_t idx = (size_t)(bid - NBX - NBW3) * 256 + tidl;
        int k = (int)(idx % KIN); size_t g = idx / KIN;
        g_wih[idx] = (k < DIN) ? __float2half_rn(W_ih[g * DIN + k]) : __float2half_rn(0.0f);
    } else {
        size_t idx = (size_t)(bid - NBX - NBW3 - NBW) * 256 + tidl;
        if (idx < B_ * H_) { g_hf[0][idx] = 0.0f; g_hh[0][idx] = __float2half_rn(0.0f); }
        if (idx < 64) g_bars[idx] = 0u;
    }
}
__global__ void bar_zero() { if (threadIdx.x < 64) g_bars[threadIdx.x] = 0u; }

// ---------------- gi GEMM (folds b_ih + b_hh for r,z gates) ----------------
__global__ __launch_bounds__(256) void gi_gemm3(const float* __restrict__ b_ih,
                                                const float* __restrict__ b_hh) {
    extern __shared__ float smf[];
    uint32_t sbase = smem_u32(smf);
    const int tid = threadIdx.x, lane = tid & 31, wid = tid >> 5;
    const int wm = (wid >> 2) * 32, wn = (wid & 3) * 24;
    const int g4 = lane >> 2, tig = lane & 3;
    const size_t m0 = (size_t)blockIdx.x * 64;
    const int n0 = blockIdx.y * 96;

    float acc[2][3][4];
#pragma unroll
    for (int i = 0; i < 2; i++)
#pragma unroll
        for (int j = 0; j < 3; j++)
#pragma unroll
            for (int e = 0; e < 4; e++) acc[i][j][e] = 0.f;

    mainloop16<KIN / BKS>(sbase, g_xh + m0 * KIN, KIN,
                          g_wih + (size_t)n0 * KIN,
                          g_wih + (size_t)(n0 + 32) * KIN,
                          g_wih + (size_t)(n0 + 64) * KIN, KIN,
                          tid, wm, wn, acc);

#pragma unroll
    for (int mt = 0; mt < 2; mt++)
#pragma unroll
        for (int nf = 0; nf < 3; nf++)
#pragma unroll
            for (int e = 0; e < 4; e++) {
                size_t row = m0 + wm + mt * 16 + g4 + ((e >> 1) << 3);
                int col = n0 + wn + nf * 8 + 2 * tig + (e & 1);
                float bias = b_ih[col] + ((col < 2 * H_) ? b_hh[col] : 0.0f);
                g_gi[row * G_ + col] = acc[mt][nf][e] + bias;
            }
}

// ---------------- persistent GRU recurrence: 512 threads, 16 warps (4m x 4n) ----------------
__global__ __launch_bounds__(512, 1) void gru_persist(const float* __restrict__ bhh) {
    extern __shared__ char smc[];
    uint32_t sb = smem_u32(smc);
    uint32_t ast = sb + W_SM;
    const int tid = threadIdx.x, lane = tid & 31, wid = tid >> 5;
    const int wm = (wid >> 2) * 16;            // 4 m-tiles of 16 rows
    const int wn8 = (wid & 3) * 8;             // 4 n-tiles of 8 cols
    const int g4 = lane >> 2, tig = lane & 3;
    const int mi = blockIdx.x >> 5, ni = blockIdx.x & 31;
    const int m0 = mi * 64, n0 = ni * 32;
    unsigned* barp = &g_bars[mi * 16];

    // ---- load W slice into smem once ----
    {
#pragma unroll 1
        for (int i = tid; i < 12288; i += 512) {
            int rr = i >> 7, cg = i & 127;
            int s = cg >> 3, c = cg & 7;
            int grow = (rr >> 5) * H_ + n0 + (rr & 31);
            uint32_t dst = sb + (uint32_t)(s * WCH + rr * 128 + ((c ^ (rr & 7)) << 4));
            cpa16(dst, g_w3 + (size_t)grow * H_ + s * 64 + c * 8);
        }
        cpcommit(); cpwait0();
        __syncthreads();
    }

    const int arow = wm + (lane & 15);
    const int acsel = (lane >> 4);
    const int browA = ((lane < 16) ? 0 : 32) + wn8 + (lane & 7);
    const int browC = 64 + wn8 + (lane & 7);
    const int bcsel = (lane >> 3) & 1;

    const int col2 = n0 + wn8 + 2 * tig;
    float2 bhn = *(const float2*)(bhh + 2 * H_ + col2);

    // register-carried h: rows {m0+wm+g4, +8} x cols {col2, col2+1}; h0 = 0
    float hc[4] = {0.f, 0.f, 0.f, 0.f};

    // gi prefetch for t=0
    float2 gir[2], giz[2], gin[2];
    {
        const float* __restrict__ gi_t = g_gi;
#pragma unroll
        for (int q = 0; q < 2; q++) {
            int row = m0 + wm + g4 + 8 * q;
            const float* p = gi_t + (size_t)row * G_ + col2;
            gir[q] = *(const float2*)(p);
            giz[q] = *(const float2*)(p + H_);
            gin[q] = *(const float2*)(p + 2 * H_);
        }
    }

#pragma unroll 1
    for (int t = 0; t < T_; t++) {
        // ---- wait for h(t) (published by all group CTAs at end of step t-1) ----
        if (t > 0) {
            if (tid == 0) {
                unsigned v; const unsigned tgt = 32u * (unsigned)t;
                do { asm volatile("ld.acquire.gpu.global.u32 %0, [%1];" : "=r"(v) : "l"(barp)); } while (v < tgt);
            }
            __syncthreads();
        }

        const __half* __restrict__ Ah = g_hh[t & 1] + (size_t)m0 * H_;

        float acc[3][4];
#pragma unroll
        for (int j = 0; j < 3; j++)
#pragma unroll
            for (int e = 0; e < 4; e++) acc[j][e] = 0.f;

        auto issueA = [&](int s) {
            int buf = s & 3;
            uint32_t ab = ast + (uint32_t)(buf * AST);
            int kc = s * 64;
            int r = tid >> 3, c = tid & 7;
            cpa16(ab + (uint32_t)(r * 128 + ((c ^ (r & 7)) << 4)),
                  Ah + (size_t)r * H_ + kc + c * 8);
            cpcommit();
        };
        issueA(0); issueA(1); issueA(2);
#pragma unroll 1
        for (int s = 0; s < 16; s++) {
            cpwait2();
            __syncthreads();
            uint32_t ab = ast + (uint32_t)((s & 3) * AST);
            uint32_t wb = sb + (uint32_t)(s * WCH);
#pragma unroll
            for (int g = 0; g < 4; g++) {
                uint32_t A0[4], B4[4], B2[2];
                {
                    int c = 2 * g + acsel;
                    LDSM4(A0[0], A0[1], A0[2], A0[3], ab + (uint32_t)(arow * 128 + ((c ^ (arow & 7)) << 4)));
                }
                {
                    int c = 2 * g + bcsel;
                    LDSM4(B4[0], B4[1], B4[2], B4[3], wb + (uint32_t)(browA * 128 + ((c ^ (browA & 7)) << 4)));
                    LDSM2(B2[0], B2[1], wb + (uint32_t)(browC * 128 + ((c ^ (browC & 7)) << 4)));
                }
                mma_f16(acc[0], A0[0], A0[1], A0[2], A0[3], B4[0], B4[1]);
                mma_f16(acc[1], A0[0], A0[1], A0[2], A0[3], B4[2], B4[3]);
                mma_f16(acc[2], A0[0], A0[1], A0[2], A0[3], B2[0], B2[1]);
            }
            if (s + 3 < 16) issueA(s + 3); else cpcommit();
        }
        cpwait0();

        // ---- register-resident gate epilogue ----
        {
            __half* __restrict__ hxB = g_hh[(t + 1) & 1];
#pragma unroll
            for (int q = 0; q < 2; q++) {
                int row = m0 + wm + g4 + 8 * q;
                float o0, o1;
                {
                    float rr = fsig(gir[q].x + acc[0][2 * q]);
                    float zz = fsig(giz[q].x + acc[1][2 * q]);
                    float nn = ftanh_(gin[q].x + rr * (acc[2][2 * q] + bhn.x));
                    o0 = (1.0f - zz) * nn + zz * hc[2 * q];
                }
                {
                    float rr = fsig(gir[q].y + acc[0][2 * q + 1]);
                    float zz = fsig(giz[q].y + acc[1][2 * q + 1]);
                    float nn = ftanh_(gin[q].y + rr * (acc[2][2 * q + 1] + bhn.y));
                    o1 = (1.0f - zz) * nn + zz * hc[2 * q + 1];
                }
                hc[2 * q] = o0; hc[2 * q + 1] = o1;
                *(__half2*)(hxB + (size_t)row * H_ + col2) = __floats2half2_rn(o0, o1);
                if (t == T_ - 1) {
                    float2 ov = { o0, o1 };
                    *(float2*)(g_hf[0] + (size_t)row * H_ + col2) = ov;
                }
            }
        }

        // ---- publish h(t+1) FIRST, then prefetch gi for t+1 ----
        __syncthreads();
        if (tid == 0)
            asm volatile("red.release.gpu.global.add.u32 [%0], 1;" :: "l"(barp) : "memory");

        if (t + 1 < T_) {
            const float* __restrict__ gi_t = g_gi + (size_t)(t + 1) * B_ * G_;
#pragma unroll
            for (int q = 0; q < 2; q++) {
                int row = m0 + wm + g4 + 8 * q;
                const float* p = gi_t + (size_t)row * G_ + col2;
                gir[q] = *(const float2*)(p);
                giz[q] = *(const float2*)(p + H_);
                gin[q] = *(const float2*)(p + 2 * H_);
            }
        }
    }
}

// ---------------- output head ----------------
__global__ void out_gemm(const float* __restrict__ Wout, const float* __restrict__ bout, float* __restrict__ out) {
    const int b = blockIdx.x;
    const int wid = threadIdx.x >> 5, lane = threadIdx.x & 31;
    const int o0 = blockIdx.y * 32 + wid * 4;
    const float* __restrict__ h = g_hf[0] + (size_t)b * H_;
    float acc[4] = {0.f, 0.f, 0.f, 0.f};
#pragma unroll
    for (int kk = 0; kk < 8; kk++) {
        int k = kk * 128 + lane * 4;
        float4 hv = *(const float4*)(h + k);
#pragma unroll
        for (int j = 0; j < 4; j++) {
            float4 w = *(const float4*)(Wout + (size_t)(o0 + j) * H_ + k);
            acc[j] += hv.x * w.x + hv.y * w.y + hv.z * w.z + hv.w * w.w;
        }
    }
#pragma unroll
    for (int j = 0; j < 4; j++) {
        float v = acc[j];
#pragma unroll
        for (int s = 16; s > 0; s >>= 1) v += __shfl_xor_sync(0xffffffffu, v, s);
        if (lane == 0) out[(size_t)b * O_ + o0 + j] = v + bout[o0 + j];
    }
}

// ---------------- launch ----------------
extern "C" void kernel_launch(void* const* d_in, const int* in_sizes, int n_in,
                              void* d_out, int out_size) {
    const float* x     = (const float*)d_in[0];
    const float* mask  = (const float*)d_in[1];
    const float* ti    = (const float*)d_in[2];
    const float* W_ih  = (const float*)d_in[3];
    const float* W_hh  = (const float*)d_in[4];
    const float* b_ih  = (const float*)d_in[5];
    const float* b_hh  = (const float*)d_in[6];
    const float* W_out = (const float*)d_in[7];
    const float* b_out = (const float*)d_in[8];
    float* out = (float*)d_out;

    static int smem_set = 0;
    if (!smem_set) {
        cudaFuncSetAttribute(gi_gemm3, cudaFuncAttributeMaxDynamicSharedMemorySize, GI_SMEM);
        cudaFuncSetAttribute(gru_persist, cudaFuncAttributeMaxDynamicSharedMemorySize, P_SMEM);
        smem_set = 1;
    }

    pack_fused<<<NBX + NBW3 + NBW + NBZ, 256>>>(x, mask, ti, W_ih, W_hh);   // 0
    gi_gemm3<<<dim3((T_ * B_) / 64, G_ / 96), 256, GI_SMEM>>>(b_ih, b_hh);  // 1
    bar_zero<<<1, 64>>>();                                                  // 2
    gru_persist<<<128, 512, P_SMEM>>>(b_hh);                                // 3 (profiled)
    out_gemm<<<dim3(B_, O_ / 32), 256>>>(W_out, b_out, out);                // 4
}

// round 13
// speedup vs baseline: 1.1795x; 1.1795x over previous
#include <cuda_runtime.h>
#include <cuda_fp16.h>
#include <cstdint>
#include <math.h>

#define B_   256
#define T_   512
#define D_   128
#define H_   1024
#define G_   3072
#define O_   128
#define DIN  257
#define KIN  320

// ---- persistent kernel smem ----
#define WCH     12288                  // one k-chunk of W: 96 rows x 128B
#define W_SM    (16 * WCH)             // 196608
#define AST     8192                   // A stage: 64 rows x 128B
#define P_SMEM  (W_SM + 4 * AST)       // 229376

// ---- gi kernel smem ----
#define GI_WSM   (5 * WCH)             // 61440 (K=320 -> 5 chunks)
#define GI_SMEM2 (GI_WSM + 4 * AST)    // 94208  -> 2 CTAs/SM
#define M_REP    8
#define GI_NSTG  (M_REP * 5)

// ---------------- scratch ----------------
__device__ float  g_gi[(size_t)T_ * B_ * G_];
__device__ __half g_xh[(size_t)(T_ * B_) * KIN];
__device__ __half g_wih[(size_t)G_ * KIN];
__device__ __half g_w3[(size_t)G_ * H_];
__device__ float  g_hf[2][B_ * H_];
__device__ __half g_hh[2][B_ * H_];
__device__ unsigned g_bars[64];

// ---------------- helpers ----------------
__device__ __forceinline__ float fsig(float x) {
    float e; asm("ex2.approx.f32 %0, %1;" : "=f"(e) : "f"(-1.4426950408889634f * x));
    float r; asm("rcp.approx.f32 %0, %1;" : "=f"(r) : "f"(1.0f + e));
    return r;
}
__device__ __forceinline__ float ftanh_(float x) {
    float e; asm("ex2.approx.f32 %0, %1;" : "=f"(e) : "f"(-2.8853900817779268f * x));
    float r; asm("rcp.approx.f32 %0, %1;" : "=f"(r) : "f"(1.0f + e));
    return 2.0f * r - 1.0f;
}
__device__ __forceinline__ uint32_t smem_u32(const void* p) {
    uint32_t a; asm("{ .reg .u64 t; cvta.to.shared.u64 t, %1; cvt.u32.u64 %0, t; }" : "=r"(a) : "l"(p)); return a;
}
__device__ __forceinline__ void cpa16(uint32_t d, const void* s) {
    asm volatile("cp.async.cg.shared.global [%0], [%1], 16;" :: "r"(d), "l"(s));
}
__device__ __forceinline__ void cpcommit() { asm volatile("cp.async.commit_group;"); }
__device__ __forceinline__ void cpwait2()  { asm volatile("cp.async.wait_group 2;" ::: "memory"); }
__device__ __forceinline__ void cpwait0()  { asm volatile("cp.async.wait_group 0;" ::: "memory"); }

#define LDSM4(r0, r1, r2, r3, addr) \
    asm volatile("ldmatrix.sync.aligned.m8n8.x4.shared.b16 {%0,%1,%2,%3}, [%4];" \
        : "=r"(r0), "=r"(r1), "=r"(r2), "=r"(r3) : "r"(addr))
#define LDSM2(r0, r1, addr) \
    asm volatile("ldmatrix.sync.aligned.m8n8.x2.shared.b16 {%0,%1}, [%2];" \
        : "=r"(r0), "=r"(r1) : "r"(addr))

__device__ __forceinline__ void mma_f16(float* d, uint32_t a0, uint32_t a1, uint32_t a2, uint32_t a3,
                                        uint32_t b0, uint32_t b1) {
    asm volatile("mma.sync.aligned.m16n8k16.row.col.f32.f16.f16.f32 "
        "{%0,%1,%2,%3},{%4,%5,%6,%7},{%8,%9},{%0,%1,%2,%3};\n"
        : "+f"(d[0]), "+f"(d[1]), "+f"(d[2]), "+f"(d[3])
        : "r"(a0), "r"(a1), "r"(a2), "r"(a3), "r"(b0), "r"(b1));
}

// ---------------- fused pack kernel ----------------
#define NBX  163840
#define NBW3 12288
#define NBW  3840
#define NBZ  1024
__global__ void pack_fused(const float* __restrict__ x, const float* __restrict__ mask,
                           const float* __restrict__ ti, const float* __restrict__ W_ih,
                           const float* __restrict__ W_hh) {
    long long bid = blockIdx.x;
    int tidl = threadIdx.x;
    if (bid < NBX) {
        size_t idx = (size_t)bid * 256 + tidl;
        int k = (int)(idx % KIN);
        size_t row = idx / KIN;
        int t = (int)(row >> 8), b = (int)(row & 255);
        float v = 0.f;
        if (k < 128) v = x[((size_t)b * T_ + t) * D_ + k];
        else if (k < 256) v = mask[((size_t)b * T_ + t) * D_ + (k - 128)];
        else if (k == 256) v = ti[(size_t)b * T_ + t];
        g_xh[idx] = __float2half_rn(v);
    } else if (bid < NBX + NBW3) {
        size_t idx = (size_t)(bid - NBX) * 256 + tidl;
        g_w3[idx] = __float2half_rn(W_hh[idx]);
    } else if (bid < NBX + NBW3 + NBW) {
        size_t idx = (size_t)(bid - NBX - NBW3) * 256 + tidl;
        int k = (int)(idx % KIN); size_t g = idx / KIN;
        g_wih[idx] = (k < DIN) ? __float2half_rn(W_ih[g * DIN + k]) : __float2half_rn(0.0f);
    } else {
        size_t idx = (size_t)(bid - NBX - NBW3 - NBW) * 256 + tidl;
        if (idx < B_ * H_) { g_hf[0][idx] = 0.0f; g_hh[0][idx] = __float2half_rn(0.0f); }
        if (idx < 64) g_bars[idx] = 0u;
    }
}
__global__ void bar_zero() { if (threadIdx.x < 64) g_bars[threadIdx.x] = 0u; }

// ---------------- gi GEMM: W_ih-resident, streams 8 A-tiles per CTA ----------------
// Grid (256, 32): blockIdx.x -> 8 consecutive 64-row A tiles; blockIdx.y -> 32-col (x3 gates) slice.
__global__ __launch_bounds__(256, 2) void gi_gemm4(const float* __restrict__ b_ih,
                                                   const float* __restrict__ b_hh) {
    extern __shared__ char smc[];
    uint32_t sb = smem_u32(smc);
    uint32_t ast = sb + GI_WSM;
    const int tid = threadIdx.x, lane = tid & 31, wid = tid >> 5;
    const int wm = (wid >> 2) * 32;
    const int wn8 = (wid & 3) * 8;
    const int g4 = lane >> 2, tig = lane & 3;
    const int ni = blockIdx.y, n0 = ni * 32;
    const size_t mbase = (size_t)blockIdx.x * (M_REP * 64);

    // ---- load W_ih slice (5 chunks x 96 rows x 128B, swizzled) ----
    {
#pragma unroll 1
        for (int i = tid; i < 5 * 96 * 8; i += 256) {
            int chunk = i / 768, rem = i % 768;
            int rr = rem >> 3, c = rem & 7;
            int grow = (rr >> 5) * H_ + n0 + (rr & 31);
            uint32_t dst = sb + (uint32_t)(chunk * WCH + rr * 128 + ((c ^ (rr & 7)) << 4));
            cpa16(dst, g_wih + (size_t)grow * KIN + chunk * 64 + c * 8);
        }
        cpcommit(); cpwait0();
        __syncthreads();
    }

    const int arow0 = wm + (lane & 15);
    const int acsel = (lane >> 4);
    const int browA = ((lane < 16) ? 0 : 32) + wn8 + (lane & 7);
    const int browC = 64 + wn8 + (lane & 7);
    const int bcsel = (lane >> 3) & 1;

    const int gcol = n0 + wn8 + 2 * tig;
    float2 biasr = { b_ih[gcol] + b_hh[gcol], b_ih[gcol + 1] + b_hh[gcol + 1] };
    float2 biasz = { b_ih[H_ + gcol] + b_hh[H_ + gcol], b_ih[H_ + gcol + 1] + b_hh[H_ + gcol + 1] };
    float2 biasn = { b_ih[2 * H_ + gcol], b_ih[2 * H_ + gcol + 1] };

    auto issueA = [&](int s) {
        int rep = s / 5, chunk = s - rep * 5;
        uint32_t ab = ast + (uint32_t)((s & 3) * AST);
        const __half* Ag = g_xh + (mbase + (size_t)rep * 64) * KIN + chunk * 64;
#pragma unroll
        for (int i = 0; i < 2; i++) {
            int f = tid + 256 * i, r = f >> 3, c = f & 7;
            cpa16(ab + (uint32_t)(r * 128 + ((c ^ (r & 7)) << 4)),
                  Ag + (size_t)r * KIN + c * 8);
        }
        cpcommit();
    };

    float acc[2][3][4];
#pragma unroll
    for (int i = 0; i < 2; i++)
#pragma unroll
        for (int j = 0; j < 3; j++)
#pragma unroll
            for (int e = 0; e < 4; e++) acc[i][j][e] = 0.f;

    issueA(0); issueA(1); issueA(2);
#pragma unroll 1
    for (int s = 0; s < GI_NSTG; s++) {
        cpwait2();
        __syncthreads();
        int rep = s / 5, chunk = s - rep * 5;
        uint32_t ab = ast + (uint32_t)((s & 3) * AST);
        uint32_t wb = sb + (uint32_t)(chunk * WCH);
#pragma unroll
        for (int g = 0; g < 4; g++) {
            uint32_t A0[4], A1[4], B4[4], B2[2];
            {
                int c = 2 * g + acsel;
                int r0 = arow0, r1 = arow0 + 16;
                LDSM4(A0[0], A0[1], A0[2], A0[3], ab + (uint32_t)(r0 * 128 + ((c ^ (r0 & 7)) << 4)));
                LDSM4(A1[0], A1[1], A1[2], A1[3], ab + (uint32_t)(r1 * 128 + ((c ^ (r1 & 7)) << 4)));
            }
            {
                int c = 2 * g + bcsel;
                LDSM4(B4[0], B4[1], B4[2], B4[3], wb + (uint32_t)(browA * 128 + ((c ^ (browA & 7)) << 4)));
                LDSM2(B2[0], B2[1], wb + (uint32_t)(browC * 128 + ((c ^ (browC & 7)) << 4)));
            }
            mma_f16(acc[0][0], A0[0], A0[1], A0[2], A0[3], B4[0], B4[1]);
            mma_f16(acc[1][0], A1[0], A1[1], A1[2], A1[3], B4[0], B4[1]);
            mma_f16(acc[0][1], A0[0], A0[1], A0[2], A0[3], B4[2], B4[3]);
            mma_f16(acc[1][1], A1[0], A1[1], A1[2], A1[3], B4[2], B4[3]);
            mma_f16(acc[0][2], A0[0], A0[1], A0[2], A0[3], B2[0], B2[1]);
            mma_f16(acc[1][2], A1[0], A1[1], A1[2], A1[3], B2[0], B2[1]);
        }
        if (s + 3 < GI_NSTG) issueA(s + 3); else cpcommit();

        if (chunk == 4) {
            // rep finished: write gi for this 64-row tile with folded biases
            size_t rowbase = mbase + (size_t)rep * 64;
#pragma unroll
            for (int mt = 0; mt < 2; mt++)
#pragma unroll
                for (int e = 0; e < 4; e++) {
                    size_t row = rowbase + wm + mt * 16 + g4 + ((e >> 1) << 3);
                    int cc = gcol + (e & 1);
                    float br = (e & 1) ? biasr.y : biasr.x;
                    float bz = (e & 1) ? biasz.y : biasz.x;
                    float bn = (e & 1) ? biasn.y : biasn.x;
                    g_gi[row * G_ + cc]          = acc[mt][0][e] + br;
                    g_gi[row * G_ + H_ + cc]     = acc[mt][1][e] + bz;
                    g_gi[row * G_ + 2 * H_ + cc] = acc[mt][2][e] + bn;
                }
#pragma unroll
            for (int i = 0; i < 2; i++)
#pragma unroll
                for (int j = 0; j < 3; j++)
#pragma unroll
                    for (int e = 0; e < 4; e++) acc[i][j][e] = 0.f;
        }
    }
    cpwait0();
}

// ---------------- persistent GRU recurrence (R11 body; wait-top / release-bottom) ----------------
__global__ __launch_bounds__(256, 1) void gru_persist(const float* __restrict__ bhh) {
    extern __shared__ char smc[];
    uint32_t sb = smem_u32(smc);
    uint32_t ast = sb + W_SM;
    const int tid = threadIdx.x, lane = tid & 31, wid = tid >> 5;
    const int wm = (wid >> 2) * 32;
    const int wn8 = (wid & 3) * 8;
    const int g4 = lane >> 2, tig = lane & 3;
    const int mi = blockIdx.x >> 5, ni = blockIdx.x & 31;
    const int m0 = mi * 64, n0 = ni * 32;
    unsigned* barp = &g_bars[mi * 16];

    // ---- load W_hh slice once ----
    {
#pragma unroll 1
        for (int i = tid; i < 12288; i += 256) {
            int rr = i >> 7, cg = i & 127;
            int s = cg >> 3, c = cg & 7;
            int grow = (rr >> 5) * H_ + n0 + (rr & 31);
            uint32_t dst = sb + (uint32_t)(s * WCH + rr * 128 + ((c ^ (rr & 7)) << 4));
            cpa16(dst, g_w3 + (size_t)grow * H_ + s * 64 + c * 8);
        }
        cpcommit(); cpwait0();
        __syncthreads();
    }

    const int arow0 = wm + (lane & 15);
    const int acsel = (lane >> 4);
    const int browA = ((lane < 16) ? 0 : 32) + wn8 + (lane & 7);
    const int browC = 64 + wn8 + (lane & 7);
    const int bcsel = (lane >> 3) & 1;

    const int col2 = n0 + wn8 + 2 * tig;
    float2 bhn = *(const float2*)(bhh + 2 * H_ + col2);

    // register-carried h: rows {m0+wm+mt*16+g4+8*rh} x cols {col2,col2+1}; h0=0
    float hc[8];
#pragma unroll
    for (int j = 0; j < 8; j++) hc[j] = 0.f;

    // gi prefetch for t=0
    float2 gir[4], giz[4], gin[4];
#pragma unroll
    for (int q = 0; q < 4; q++) {
        int row = m0 + wm + (q >> 1) * 16 + g4 + 8 * (q & 1);
        const float* p = g_gi + (size_t)row * G_ + col2;
        gir[q] = *(const float2*)(p);
        giz[q] = *(const float2*)(p + H_);
        gin[q] = *(const float2*)(p + 2 * H_);
    }

#pragma unroll 1
    for (int t = 0; t < T_; t++) {
        // ---- wait for h(t) ----
        if (t > 0) {
            if (tid == 0) {
                unsigned v; const unsigned tgt = 32u * (unsigned)t;
                do { asm volatile("ld.acquire.gpu.global.u32 %0, [%1];" : "=r"(v) : "l"(barp)); } while (v < tgt);
            }
            __syncthreads();
        }

        const __half* __restrict__ Ah = g_hh[t & 1] + (size_t)m0 * H_;

        float acc[2][3][4];
#pragma unroll
        for (int i = 0; i < 2; i++)
#pragma unroll
            for (int j = 0; j < 3; j++)
#pragma unroll
                for (int e = 0; e < 4; e++) acc[i][j][e] = 0.f;

        auto issueA = [&](int s) {
            int buf = s & 3;
            uint32_t ab = ast + (uint32_t)(buf * AST);
            int kc = s * 64;
#pragma unroll
            for (int i = 0; i < 2; i++) {
                int f = tid + 256 * i, r = f >> 3, c = f & 7;
                cpa16(ab + (uint32_t)(r * 128 + ((c ^ (r & 7)) << 4)),
                      Ah + (size_t)r * H_ + kc + c * 8);
            }
            cpcommit();
        };
        issueA(0); issueA(1); issueA(2);
#pragma unroll 1
        for (int s = 0; s < 16; s++) {
            cpwait2();
            __syncthreads();
            uint32_t ab = ast + (uint32_t)((s & 3) * AST);
            uint32_t wb = sb + (uint32_t)(s * WCH);
#pragma unroll
            for (int g = 0; g < 4; g++) {
                uint32_t A0[4], A1[4], B4[4], B2[2];
                {
                    int c = 2 * g + acsel;
                    int r0 = arow0, r1 = arow0 + 16;
                    LDSM4(A0[0], A0[1], A0[2], A0[3], ab + (uint32_t)(r0 * 128 + ((c ^ (r0 & 7)) << 4)));
                    LDSM4(A1[0], A1[1], A1[2], A1[3], ab + (uint32_t)(r1 * 128 + ((c ^ (r1 & 7)) << 4)));
                }
                {
                    int c = 2 * g + bcsel;
                    LDSM4(B4[0], B4[1], B4[2], B4[3], wb + (uint32_t)(browA * 128 + ((c ^ (browA & 7)) << 4)));
                    LDSM2(B2[0], B2[1], wb + (uint32_t)(browC * 128 + ((c ^ (browC & 7)) << 4)));
                }
                mma_f16(acc[0][0], A0[0], A0[1], A0[2], A0[3], B4[0], B4[1]);
                mma_f16(acc[1][0], A1[0], A1[1], A1[2], A1[3], B4[0], B4[1]);
                mma_f16(acc[0][1], A0[0], A0[1], A0[2], A0[3], B4[2], B4[3]);
                mma_f16(acc[1][1], A1[0], A1[1], A1[2], A1[3], B4[2], B4[3]);
                mma_f16(acc[0][2], A0[0], A0[1], A0[2], A0[3], B2[0], B2[1]);
                mma_f16(acc[1][2], A1[0], A1[1], A1[2], A1[3], B2[0], B2[1]);
            }
            if (s + 3 < 16) issueA(s + 3); else cpcommit();
        }
        cpwait0();

        // ---- register-resident gate epilogue (biases for r,z folded in gi) ----
        {
            __half* __restrict__ hxB = g_hh[(t + 1) & 1];
#pragma unroll
            for (int q = 0; q < 4; q++) {
                int mt = q >> 1, rh = q & 1;
                int row = m0 + wm + mt * 16 + g4 + 8 * rh;
                float o0, o1;
                {
                    float rr = fsig(gir[q].x + acc[mt][0][2 * rh]);
                    float zz = fsig(giz[q].x + acc[mt][1][2 * rh]);
                    float nn = ftanh_(gin[q].x + rr * (acc[mt][2][2 * rh] + bhn.x));
                    o0 = (1.0f - zz) * nn + zz * hc[2 * q];
                }
                {
                    float rr = fsig(gir[q].y + acc[mt][0][2 * rh + 1]);
                    float zz = fsig(giz[q].y + acc[mt][1][2 * rh + 1]);
                    float nn = ftanh_(gin[q].y + rr * (acc[mt][2][2 * rh + 1] + bhn.y));
                    o1 = (1.0f - zz) * nn + zz * hc[2 * q + 1];
                }
                hc[2 * q] = o0; hc[2 * q + 1] = o1;
                *(__half2*)(hxB + (size_t)row * H_ + col2) = __floats2half2_rn(o0, o1);
                if (t == T_ - 1) {
                    float2 ov = { o0, o1 };
                    *(float2*)(g_hf[0] + (size_t)row * H_ + col2) = ov;
                }
            }
        }

        // ---- publish h(t+1), then prefetch gi(t+1) ----
        __syncthreads();
        if (tid == 0)
            asm volatile("red.release.gpu.global.add.u32 [%0], 1;" :: "l"(barp) : "memory");

        if (t + 1 < T_) {
            const float* __restrict__ gi_t = g_gi + (size_t)(t + 1) * B_ * G_;
#pragma unroll
            for (int q = 0; q < 4; q++) {
                int row = m0 + wm + (q >> 1) * 16 + g4 + 8 * (q & 1);
                const float* p = gi_t + (size_t)row * G_ + col2;
                gir[q] = *(const float2*)(p);
                giz[q] = *(const float2*)(p + H_);
                gin[q] = *(const float2*)(p + 2 * H_);
            }
        }
    }
}

// ---------------- output head ----------------
__global__ void out_gemm(const float* __restrict__ Wout, const float* __restrict__ bout, float* __restrict__ out) {
    const int b = blockIdx.x;
    const int wid = threadIdx.x >> 5, lane = threadIdx.x & 31;
    const int o0 = blockIdx.y * 32 + wid * 4;
    const float* __restrict__ h = g_hf[0] + (size_t)b * H_;
    float acc[4] = {0.f, 0.f, 0.f, 0.f};
#pragma unroll
    for (int kk = 0; kk < 8; kk++) {
        int k = kk * 128 + lane * 4;
        float4 hv = *(const float4*)(h + k);
#pragma unroll
        for (int j = 0; j < 4; j++) {
            float4 w = *(const float4*)(Wout + (size_t)(o0 + j) * H_ + k);
            acc[j] += hv.x * w.x + hv.y * w.y + hv.z * w.z + hv.w * w.w;
        }
    }
#pragma unroll
    for (int j = 0; j < 4; j++) {
        float v = acc[j];
#pragma unroll
        for (int s = 16; s > 0; s >>= 1) v += __shfl_xor_sync(0xffffffffu, v, s);
        if (lane == 0) out[(size_t)b * O_ + o0 + j] = v + bout[o0 + j];
    }
}

// ---------------- launch ----------------
extern "C" void kernel_launch(void* const* d_in, const int* in_sizes, int n_in,
                              void* d_out, int out_size) {
    const float* x     = (const float*)d_in[0];
    const float* mask  = (const float*)d_in[1];
    const float* ti    = (const float*)d_in[2];
    const float* W_ih  = (const float*)d_in[3];
    const float* W_hh  = (const float*)d_in[4];
    const float* b_ih  = (const float*)d_in[5];
    const float* b_hh  = (const float*)d_in[6];
    const float* W_out = (const float*)d_in[7];
    const float* b_out = (const float*)d_in[8];
    float* out = (float*)d_out;

    static int smem_set = 0;
    if (!smem_set) {
        cudaFuncSetAttribute(gi_gemm4, cudaFuncAttributeMaxDynamicSharedMemorySize, GI_SMEM2);
        cudaFuncSetAttribute(gru_persist, cudaFuncAttributeMaxDynamicSharedMemorySize, P_SMEM);
        smem_set = 1;
    }

    pack_fused<<<NBX + NBW3 + NBW + NBZ, 256>>>(x, mask, ti, W_ih, W_hh);       // 0
    gi_gemm4<<<dim3((T_ * B_) / (M_REP * 64), 32), 256, GI_SMEM2>>>(b_ih, b_hh); // 1
    bar_zero<<<1, 64>>>();                                                       // 2
    gru_persist<<<128, 256, P_SMEM>>>(b_hh);                                     // 3 (profiled)
    out_gemm<<<dim3(B_, O_ / 32), 256>>>(W_out, b_out, out);                     // 4
}